// round 16
// baseline (speedup 1.0000x reference)
#include <cuda_runtime.h>

#define ATT_H 128
#define KVH   256
#define NB    2
#define NS    1024
#define NQ    512
#define SK2   32
#define NSC   16                        // pgemm split-s count
#define NROWS (NB*NS + NB*NQ)           // 3072 projection rows

// scratch (no allocations allowed)
__device__ float g_pp  [2*NROWS*ATT_H]; // proj k-split partials (score reads both halves)
__device__ float g_E   [NB*NQ*NS];      // [b][q][s] raw exp(score)
__device__ float g_ET  [NB*NS*NQ];      // [b][s][q] transposed copy
__device__ float g_part[NSC*NB*NQ*KVH]; // split-s partial GEMM results
__device__ float g_inv [NB*NQ];

__device__ __forceinline__ float fast_tanh(float x){ float y; asm("tanh.approx.f32 %0, %1;" : "=f"(y) : "f"(x)); return y; }
__device__ __forceinline__ float fast_ex2 (float x){ float y; asm("ex2.approx.f32 %0, %1;"  : "=f"(y) : "f"(x)); return y; }

__device__ __forceinline__ float2 ffma2(float2 a, float2 b, float2 c) {
    float2 d;
    asm("fma.rn.f32x2 %0, %1, %2, %3;"
        : "=l"(reinterpret_cast<unsigned long long&>(d))
        : "l"(reinterpret_cast<unsigned long long&>(a)),
          "l"(reinterpret_cast<unsigned long long&>(b)),
          "l"(reinterpret_cast<unsigned long long&>(c)));
    return d;
}

__device__ __forceinline__ void cp16(void* dst, const void* src) {
    unsigned d = (unsigned)__cvta_generic_to_shared(dst);
    asm volatile("cp.async.cg.shared.global [%0], [%1], 16;" :: "r"(d), "l"(src));
}
__device__ __forceinline__ void cp_commit() { asm volatile("cp.async.commit_group;"); }
__device__ __forceinline__ void cp_wait0()  { asm volatile("cp.async.wait_group 0;" ::: "memory"); }
__device__ __forceinline__ void cp_wait1()  { asm volatile("cp.async.wait_group 1;" ::: "memory"); }

// ---------------- Kernel 1: proj partials — cp.async pipelined, 16-row blocks ----------------
// Block: 16 rows x 64 cols (ch) x 128 k (kh), 256 thr, thread tile 2r x 2c. Grid 768.
__global__ void __launch_bounds__(256) proj_kernel(
    const float* __restrict__ kv, const float* __restrict__ qy,
    const float* __restrict__ Wkv, const float* __restrict__ Wq)
{
    __shared__ float Wb [2][32*64];   // 8KB each
    __shared__ float inT[2][32*18];   // [kk][r] transposed, pad 18

    const int tid = threadIdx.x;
    const int rb  = blockIdx.x;       // 768 = 192 rowblk * 2 ch * 2 kh
    const int kh  = rb & 1;
    const int ch  = (rb >> 1) & 1;
    const int row0g = (rb >> 2) * 16;

    const float *in, *W;
    if (row0g < NB*NS) { in = kv + (size_t)row0g*256;           W = Wkv; }
    else               { in = qy + (size_t)(row0g - NB*NS)*256; W = Wq;  }
    in += kh*128;
    W  += (size_t)kh*128*128 + ch*64;

    const int ir  = tid >> 3;         // 0..31 (valid rows: <16 -> threads 0..127)
    const int ik4 = tid & 7;
    const bool inldr = (tid < 128);

    #define CPW(c, buf) { \
        _Pragma("unroll") for (int j = 0; j < 2; j++) { \
            int idx = tid + 256*j; int kk = idx >> 4, c4 = idx & 15; \
            cp16(&Wb[buf][kk*64 + c4*4], W + (size_t)((c)*32 + kk)*128 + c4*4); } \
        cp_commit(); }

    #define LDGIN(c) (*(const float4*)(in + (size_t)ir*256 + (c)*32 + ik4*4))

    #define STSIN(c, v) { \
        inT[(c)&1][(ik4*4+0)*18 + ir] = (v).x; \
        inT[(c)&1][(ik4*4+1)*18 + ir] = (v).y; \
        inT[(c)&1][(ik4*4+2)*18 + ir] = (v).z; \
        inT[(c)&1][(ik4*4+3)*18 + ir] = (v).w; }

    const int tx = tid & 31;          // c pair
    const int ty = tid >> 5;          // 0..7 -> rows ty*2, ty*2+1

    float2 acc[2];
    acc[0] = make_float2(0.f, 0.f);
    acc[1] = make_float2(0.f, 0.f);

    // prologue
    CPW(0, 0);
    float4 iv = make_float4(0.f,0.f,0.f,0.f);
    if (inldr) iv = LDGIN(0);
    CPW(1, 1);
    if (inldr) STSIN(0, iv);
    cp_wait1();
    __syncthreads();

    for (int kc = 0; kc < 4; kc++) {
        const int buf = kc & 1;
        if (kc < 3 && inldr) iv = LDGIN(kc + 1);

        const float* Wp = Wb[buf];
        const float* Ip = inT[buf];
        #pragma unroll 8
        for (int kk = 0; kk < 32; kk++) {
            float2 w2  = *(const float2*)&Wp[kk*64 + tx*2];
            float2 i01 = *(const float2*)&Ip[kk*18 + ty*2];
            acc[0] = ffma2(w2, make_float2(i01.x, i01.x), acc[0]);
            acc[1] = ffma2(w2, make_float2(i01.y, i01.y), acc[1]);
        }
        __syncthreads();                       // everyone done reading buf

        if (kc < 2) CPW(kc + 2, buf);          // refill W into just-freed buf
        if (kc < 3) {
            if (inldr) STSIN(kc + 1, iv);      // in chunk kc+1 -> inT[buf^1]
            if (kc == 2) cp_wait0(); else cp_wait1();
            __syncthreads();
        }
    }

    float* outp = g_pp + (size_t)kh*NROWS*ATT_H + (size_t)(row0g + ty*2)*ATT_H + ch*64 + tx*2;
    *(float2*)outp           = acc[0];
    *(float2*)(outp + ATT_H) = acc[1];
    #undef CPW
    #undef LDGIN
    #undef STSIN
}

// ---------------- Kernel 2: score — fp32 tanh (R14 proven). Grid 2048. ----------------
__global__ void __launch_bounds__(256) score_kernel(
    const float* __restrict__ wv_g, const float* __restrict__ bv_g,
    const float* __restrict__ bkv_g, const float* __restrict__ bq_g)
{
    __shared__ float4 pk_sh[64*33];
    __shared__ float4 pq_sh[8*32];
    __shared__ float4 wv_sh[32];
    __shared__ float  ET_sh[64*9];

    const int tid = threadIdx.x;
    const int bid = blockIdx.x;
    const int st  = bid & 15;
    const int qt  = bid >> 4;
    const int b   = qt >> 6;
    const int q0  = (qt & 63) * 8;
    const int s0  = st * 64;

    const float4* pp0 = (const float4*)g_pp;
    const float4* pp1 = pp0 + NROWS*(ATT_H/4);

    {
        int q = tid >> 5, a4 = tid & 31;
        size_t r = (size_t)(NB*NS + b*NQ + q0 + q)*32 + a4;
        float4 v0 = pp0[r], v1 = pp1[r];
        float4 bk = ((const float4*)bkv_g)[a4];
        float4 bq = ((const float4*)bq_g)[a4];
        pq_sh[q*32 + a4] = make_float4(v0.x+v1.x+bk.x+bq.x, v0.y+v1.y+bk.y+bq.y,
                                       v0.z+v1.z+bk.z+bq.z, v0.w+v1.w+bk.w+bq.w);
    }
    if (tid < 32) wv_sh[tid] = ((const float4*)wv_g)[tid];
    #pragma unroll
    for (int i = 0; i < 8; i++) {
        int f4 = tid + 256*i;
        int row = f4 >> 5, c4 = f4 & 31;
        size_t r = (size_t)(b*NS + s0 + row)*32 + c4;
        float4 v0 = pp0[r], v1 = pp1[r];
        pk_sh[row*33 + c4] = make_float4(v0.x+v1.x, v0.y+v1.y, v0.z+v1.z, v0.w+v1.w);
    }
    __syncthreads();

    const float bv = __ldg(bv_g);
    const int sl = tid & 63;
    const int qq = tid >> 6;

    float acc0 = 0.f, acc1 = 0.f;
    const float4* pkp  = pk_sh + sl*33;
    const float4* pq0p = pq_sh + (2*qq    )*32;
    const float4* pq1p = pq_sh + (2*qq + 1)*32;

    #pragma unroll 8
    for (int a4 = 0; a4 < 32; a4++) {
        float4 pk = pkp[a4];
        float4 w  = wv_sh[a4];
        float4 p0 = pq0p[a4];
        float4 p1 = pq1p[a4];
        acc0 += w.x * fast_tanh(pk.x + p0.x);
        acc0 += w.y * fast_tanh(pk.y + p0.y);
        acc0 += w.z * fast_tanh(pk.z + p0.z);
        acc0 += w.w * fast_tanh(pk.w + p0.w);
        acc1 += w.x * fast_tanh(pk.x + p1.x);
        acc1 += w.y * fast_tanh(pk.y + p1.y);
        acc1 += w.z * fast_tanh(pk.z + p1.z);
        acc1 += w.w * fast_tanh(pk.w + p1.w);
    }
    float e0 = fast_ex2((acc0 + bv) * 1.44269504f);
    float e1 = fast_ex2((acc1 + bv) * 1.44269504f);

    float* Eout = g_E + (size_t)(b*NQ + q0 + 2*qq)*NS + s0 + sl;
    Eout[0]  = e0;
    Eout[NS] = e1;

    ET_sh[sl*9 + 2*qq]     = e0;
    ET_sh[sl*9 + 2*qq + 1] = e1;
    __syncthreads();
    {
        int s_local = tid >> 2, qp = tid & 3;
        float2 v = make_float2(ET_sh[s_local*9 + qp*2], ET_sh[s_local*9 + qp*2 + 1]);
        *(float2*)(g_ET + ((size_t)b*NS + s0 + s_local)*NQ + q0 + qp*2) = v;
    }
}

// ---------------- Kernel 3: row sums -> g_inv + normalized weights. Grid 256. ----------------
__global__ void __launch_bounds__(128) rowsum_kernel(float* __restrict__ out_w)
{
    const int tid  = threadIdx.x;
    const int lane = tid & 31;
    const int row  = blockIdx.x*4 + (tid >> 5);

    const float4* src = (const float4*)(g_E + (size_t)row*NS);
    float4 v[8];
    float s = 0.f;
    #pragma unroll
    for (int i = 0; i < 8; i++) {
        v[i] = src[lane + 32*i];
        s += (v[i].x + v[i].y) + (v[i].z + v[i].w);
    }
    #pragma unroll
    for (int o = 16; o > 0; o >>= 1) s += __shfl_xor_sync(0xffffffffu, s, o);
    const float inv = 1.0f / s;
    if (lane == 0) g_inv[row] = inv;

    float4* dst = (float4*)(out_w + (size_t)row*NS);
    #pragma unroll
    for (int i = 0; i < 8; i++) {
        v[i].x *= inv; v[i].y *= inv; v[i].z *= inv; v[i].w *= inv;
        dst[lane + 32*i] = v[i];
    }
}

// ---------------- Kernel 4: pgemm — 256-thr blocks, ~3 blocks/SM (R13 proven) ----------------
__global__ void __launch_bounds__(256) pgemm_kernel(const float* __restrict__ kv)
{
    extern __shared__ float ps[];
    float* kvs = ps;                    // 2 * 32*128
    float* Es  = ps + 2*SK2*128;        // 2 * 32*64

    const int tid = threadIdx.x;
    const int bid = blockIdx.x;
    const int sc  = bid & 15;
    const int hh  = (bid >> 4) & 1;
    const int qt  = bid >> 5;           // 0..15
    const int row0 = qt * 64;
    const int b   = qt >> 3;
    const int qcol = (qt & 7) * 64;
    const int s0  = sc * 64;

    const float* kvg = kv   + ((size_t)b*NS + s0)*KVH + hh*128;
    const float* Eg  = g_ET + ((size_t)b*NS + s0)*NQ + qcol;

    const int tx = tid & 31;
    const int ty = tid >> 5;

    #define ISSUE2(c, buf) { \
        _Pragma("unroll") for (int j = 0; j < 4; j++) { \
            int i = tid + 256*j; int s = i >> 5, h4 = i & 31; \
            cp16(kvs + (buf)*SK2*128 + s*128 + h4*4, \
                 kvg + (size_t)((c)*SK2 + s)*KVH + h4*4); } \
        _Pragma("unroll") for (int j = 0; j < 2; j++) { \
            int i = tid + 256*j; int s = i >> 4, q4 = i & 15; \
            cp16(Es + (buf)*SK2*64 + s*64 + q4*4, \
                 Eg + (size_t)((c)*SK2 + s)*NQ + q4*4); } \
        cp_commit(); }

    ISSUE2(0, 0);
    ISSUE2(1, 1);

    float2 acc[8][2];
    #pragma unroll
    for (int i = 0; i < 8; i++) { acc[i][0] = make_float2(0.f,0.f); acc[i][1] = make_float2(0.f,0.f); }

    #pragma unroll
    for (int c = 0; c < 2; c++) {
        if (c == 0) cp_wait1(); else cp_wait0();
        __syncthreads();
        const float* kvb = kvs + c*SK2*128;
        const float* Eb  = Es  + c*SK2*64;
        #pragma unroll 8
        for (int k = 0; k < SK2; k++) {
            float4 k4 = ((const float4*)(kvb + k*128))[tx];
            float4 e0 = ((const float4*)(Eb  + k*64))[ty*2];
            float4 e1 = ((const float4*)(Eb  + k*64))[ty*2 + 1];
            float2 kp0 = make_float2(k4.x, k4.y);
            float2 kp1 = make_float2(k4.z, k4.w);
            float ev[8] = { e0.x, e0.y, e0.z, e0.w, e1.x, e1.y, e1.z, e1.w };
            #pragma unroll
            for (int qi = 0; qi < 8; qi++) {
                float2 eb = make_float2(ev[qi], ev[qi]);
                acc[qi][0] = ffma2(kp0, eb, acc[qi][0]);
                acc[qi][1] = ffma2(kp1, eb, acc[qi][1]);
            }
        }
        __syncthreads();
    }

    float* pb = g_part + ((size_t)sc*(NB*NQ) + row0 + ty*8)*KVH + hh*128 + tx*4;
    #pragma unroll
    for (int qi = 0; qi < 8; qi++)
        *(float4*)(pb + (size_t)qi*KVH) =
            make_float4(acc[qi][0].x, acc[qi][0].y, acc[qi][1].x, acc[qi][1].y);
    #undef ISSUE2
}

// ---------------- Kernel 5: combine 16 partials + normalize (L2-resident) ----------------
__global__ void __launch_bounds__(256) combine_kernel(float* __restrict__ out_o)
{
    const int idx = blockIdx.x*256 + threadIdx.x;
    const int row = idx >> 6;
    const float inv = g_inv[row];
    float4 s = make_float4(0.f,0.f,0.f,0.f);
    #pragma unroll
    for (int c = 0; c < NSC; c++) {
        float4 p = ((const float4*)g_part)[(size_t)c*(NB*NQ*KVH/4) + idx];
        s.x += p.x; s.y += p.y; s.z += p.z; s.w += p.w;
    }
    s.x *= inv; s.y *= inv; s.z *= inv; s.w *= inv;
    ((float4*)out_o)[idx] = s;
}

extern "C" void kernel_launch(void* const* d_in, const int* in_sizes, int n_in,
                              void* d_out, int out_size)
{
    const float* kv  = (const float*)d_in[0];
    const float* qy  = (const float*)d_in[1];
    const float* Wkv = (const float*)d_in[2];
    const float* bkv = (const float*)d_in[3];
    const float* Wq  = (const float*)d_in[4];
    const float* bq  = (const float*)d_in[5];
    const float* wv  = (const float*)d_in[6];
    const float* bv  = (const float*)d_in[7];

    float* out_o = (float*)d_out;
    float* out_w = out_o + NB*NQ*KVH;

    const int pg_smem = (2*SK2*128 + 2*SK2*64) * 4;   // 48KB

    static cudaStream_t s1 = nullptr;
    static cudaEvent_t evS = nullptr, evJ = nullptr;
    if (!s1) {
        cudaStreamCreateWithFlags(&s1, cudaStreamNonBlocking);
        cudaEventCreateWithFlags(&evS, cudaEventDisableTiming);
        cudaEventCreateWithFlags(&evJ, cudaEventDisableTiming);
        cudaFuncSetAttribute(pgemm_kernel, cudaFuncAttributeMaxDynamicSharedMemorySize, pg_smem);
    }

    proj_kernel <<<768, 256>>>(kv, qy, Wkv, Wq);
    score_kernel<<<2048, 256>>>(wv, bv, bkv, bq);

    // after score: pgemm on s1, rowsum on default — complementary pipes
    cudaEventRecord(evS, 0);
    cudaStreamWaitEvent(s1, evS, 0);
    pgemm_kernel <<<512, 256, pg_smem, s1>>>(kv);
    rowsum_kernel<<<256, 128>>>(out_w);

    // join
    cudaEventRecord(evJ, s1);
    cudaStreamWaitEvent((cudaStream_t)0, evJ, 0);
    combine_kernel<<<256, 256>>>(out_o);
}

// round 17
// speedup vs baseline: 1.0188x; 1.0188x over previous
#include <cuda_runtime.h>

#define ATT_H 128
#define KVH   256
#define NB    2
#define NS    1024
#define NQ    512
#define SK2   32
#define NSC   16                        // pgemm split-s count (8 per half)
#define NROWS (NB*NS + NB*NQ)           // 3072 projection rows

// scratch (no allocations allowed)
__device__ float g_pp  [2*NROWS*ATT_H]; // proj k-split partials (score reads both halves)
__device__ float g_E   [NB*NQ*NS];      // [b][q][s] raw exp(score)
__device__ float g_ET  [NB*NS*NQ];      // [b][s][q] transposed copy
__device__ float g_part[NSC*NB*NQ*KVH]; // split-s partial GEMM results
__device__ float g_inv [NB*NQ];

__device__ __forceinline__ float fast_tanh(float x){ float y; asm("tanh.approx.f32 %0, %1;" : "=f"(y) : "f"(x)); return y; }
__device__ __forceinline__ float fast_ex2 (float x){ float y; asm("ex2.approx.f32 %0, %1;"  : "=f"(y) : "f"(x)); return y; }

__device__ __forceinline__ float2 ffma2(float2 a, float2 b, float2 c) {
    float2 d;
    asm("fma.rn.f32x2 %0, %1, %2, %3;"
        : "=l"(reinterpret_cast<unsigned long long&>(d))
        : "l"(reinterpret_cast<unsigned long long&>(a)),
          "l"(reinterpret_cast<unsigned long long&>(b)),
          "l"(reinterpret_cast<unsigned long long&>(c)));
    return d;
}

__device__ __forceinline__ void cp16(void* dst, const void* src) {
    unsigned d = (unsigned)__cvta_generic_to_shared(dst);
    asm volatile("cp.async.cg.shared.global [%0], [%1], 16;" :: "r"(d), "l"(src));
}
__device__ __forceinline__ void cp_commit() { asm volatile("cp.async.commit_group;"); }
__device__ __forceinline__ void cp_wait0()  { asm volatile("cp.async.wait_group 0;" ::: "memory"); }
__device__ __forceinline__ void cp_wait1()  { asm volatile("cp.async.wait_group 1;" ::: "memory"); }

// ---------------- Kernel 1: proj partials — cp.async pipelined (R14 proven), per-half ----------------
// Grid 192 per half: 48 rowblk (32 kv-rowblk + 16 q-rowblk) * 2 ch * 2 kh.
__global__ void __launch_bounds__(256) proj_kernel(
    const float* __restrict__ kv, const float* __restrict__ qy,
    const float* __restrict__ Wkv, const float* __restrict__ Wq,
    int rb_kv_base, int rb_q_base)
{
    __shared__ float Wb [2][32*64];
    __shared__ float inT[2][32*34];

    const int tid = threadIdx.x;
    const int rb  = blockIdx.x;       // 192 = 48 rowblk * 2 ch * 2 kh
    const int kh  = rb & 1;
    const int ch  = (rb >> 1) & 1;
    const int rbk = rb >> 2;          // 0..47
    const int rowblk = (rbk < 32) ? (rb_kv_base + rbk) : (rb_q_base + (rbk - 32));
    const int row0g = rowblk * 32;

    const float *in, *W;
    if (row0g < NB*NS) { in = kv + (size_t)row0g*256;           W = Wkv; }
    else               { in = qy + (size_t)(row0g - NB*NS)*256; W = Wq;  }
    in += kh*128;
    W  += (size_t)kh*128*128 + ch*64;

    const int ir  = tid >> 3;
    const int ik4 = tid & 7;

    #define CPW(c, buf) { \
        _Pragma("unroll") for (int j = 0; j < 2; j++) { \
            int idx = tid + 256*j; int kk = idx >> 4, c4 = idx & 15; \
            cp16(&Wb[buf][kk*64 + c4*4], W + (size_t)((c)*32 + kk)*128 + c4*4); } \
        cp_commit(); }

    #define LDGIN(c) (*(const float4*)(in + (size_t)ir*256 + (c)*32 + ik4*4))

    #define STSIN(c, v) { \
        inT[(c)&1][(ik4*4+0)*34 + ir] = (v).x; \
        inT[(c)&1][(ik4*4+1)*34 + ir] = (v).y; \
        inT[(c)&1][(ik4*4+2)*34 + ir] = (v).z; \
        inT[(c)&1][(ik4*4+3)*34 + ir] = (v).w; }

    const int tx = tid & 31;
    const int ty = tid >> 5;

    float2 acc[4];
    #pragma unroll
    for (int i = 0; i < 4; i++) acc[i] = make_float2(0.f, 0.f);

    CPW(0, 0);
    float4 iv = LDGIN(0);
    CPW(1, 1);
    STSIN(0, iv);
    cp_wait1();
    __syncthreads();

    for (int kc = 0; kc < 4; kc++) {
        const int buf = kc & 1;
        if (kc < 3) iv = LDGIN(kc + 1);

        const float* Wp = Wb[buf];
        const float* Ip = inT[buf];
        #pragma unroll 8
        for (int kk = 0; kk < 32; kk++) {
            float2 w2  = *(const float2*)&Wp[kk*64 + tx*2];
            float2 i01 = *(const float2*)&Ip[kk*34 + ty*4];
            float2 i23 = *(const float2*)&Ip[kk*34 + ty*4 + 2];
            acc[0] = ffma2(w2, make_float2(i01.x, i01.x), acc[0]);
            acc[1] = ffma2(w2, make_float2(i01.y, i01.y), acc[1]);
            acc[2] = ffma2(w2, make_float2(i23.x, i23.x), acc[2]);
            acc[3] = ffma2(w2, make_float2(i23.y, i23.y), acc[3]);
        }
        __syncthreads();

        if (kc < 2) CPW(kc + 2, buf);
        if (kc < 3) {
            STSIN(kc + 1, iv);
            if (kc == 2) cp_wait0(); else cp_wait1();
            __syncthreads();
        }
    }

    float* outp = g_pp + (size_t)kh*NROWS*ATT_H + (size_t)(row0g + ty*4)*ATT_H + ch*64 + tx*2;
    #pragma unroll
    for (int ri = 0; ri < 4; ri++)
        *(float2*)(outp + (size_t)ri*ATT_H) = acc[ri];
    #undef CPW
    #undef LDGIN
    #undef STSIN
}

// ---------------- Kernel 2: score — fp32 tanh (R14 proven), per-half. Grid 1024. ----------------
__global__ void __launch_bounds__(256) score_kernel(
    const float* __restrict__ wv_g, const float* __restrict__ bv_g,
    const float* __restrict__ bkv_g, const float* __restrict__ bq_g, int b)
{
    __shared__ float4 pk_sh[64*33];
    __shared__ float4 pq_sh[8*32];
    __shared__ float4 wv_sh[32];
    __shared__ float  ET_sh[64*9];

    const int tid = threadIdx.x;
    const int bid = blockIdx.x;        // 1024 = 64 qt * 16 st
    const int st  = bid & 15;
    const int qt  = bid >> 4;          // 0..63
    const int q0  = qt * 8;
    const int s0  = st * 64;

    const float4* pp0 = (const float4*)g_pp;
    const float4* pp1 = pp0 + NROWS*(ATT_H/4);

    {
        int q = tid >> 5, a4 = tid & 31;
        size_t r = (size_t)(NB*NS + b*NQ + q0 + q)*32 + a4;
        float4 v0 = pp0[r], v1 = pp1[r];
        float4 bk = ((const float4*)bkv_g)[a4];
        float4 bq = ((const float4*)bq_g)[a4];
        pq_sh[q*32 + a4] = make_float4(v0.x+v1.x+bk.x+bq.x, v0.y+v1.y+bk.y+bq.y,
                                       v0.z+v1.z+bk.z+bq.z, v0.w+v1.w+bk.w+bq.w);
    }
    if (tid < 32) wv_sh[tid] = ((const float4*)wv_g)[tid];
    #pragma unroll
    for (int i = 0; i < 8; i++) {
        int f4 = tid + 256*i;
        int row = f4 >> 5, c4 = f4 & 31;
        size_t r = (size_t)(b*NS + s0 + row)*32 + c4;
        float4 v0 = pp0[r], v1 = pp1[r];
        pk_sh[row*33 + c4] = make_float4(v0.x+v1.x, v0.y+v1.y, v0.z+v1.z, v0.w+v1.w);
    }
    __syncthreads();

    const float bv = __ldg(bv_g);
    const int sl = tid & 63;
    const int qq = tid >> 6;

    float acc0 = 0.f, acc1 = 0.f;
    const float4* pkp  = pk_sh + sl*33;
    const float4* pq0p = pq_sh + (2*qq    )*32;
    const float4* pq1p = pq_sh + (2*qq + 1)*32;

    #pragma unroll 8
    for (int a4 = 0; a4 < 32; a4++) {
        float4 pk = pkp[a4];
        float4 w  = wv_sh[a4];
        float4 p0 = pq0p[a4];
        float4 p1 = pq1p[a4];
        acc0 += w.x * fast_tanh(pk.x + p0.x);
        acc0 += w.y * fast_tanh(pk.y + p0.y);
        acc0 += w.z * fast_tanh(pk.z + p0.z);
        acc0 += w.w * fast_tanh(pk.w + p0.w);
        acc1 += w.x * fast_tanh(pk.x + p1.x);
        acc1 += w.y * fast_tanh(pk.y + p1.y);
        acc1 += w.z * fast_tanh(pk.z + p1.z);
        acc1 += w.w * fast_tanh(pk.w + p1.w);
    }
    float e0 = fast_ex2((acc0 + bv) * 1.44269504f);
    float e1 = fast_ex2((acc1 + bv) * 1.44269504f);

    float* Eout = g_E + (size_t)(b*NQ + q0 + 2*qq)*NS + s0 + sl;
    Eout[0]  = e0;
    Eout[NS] = e1;

    ET_sh[sl*9 + 2*qq]     = e0;
    ET_sh[sl*9 + 2*qq + 1] = e1;
    __syncthreads();
    {
        int s_local = tid >> 2, qp = tid & 3;
        float2 v = make_float2(ET_sh[s_local*9 + qp*2], ET_sh[s_local*9 + qp*2 + 1]);
        *(float2*)(g_ET + ((size_t)b*NS + s0 + s_local)*NQ + q0 + qp*2) = v;
    }
}

// ---------------- Kernel 3: row sums -> g_inv + normalized weights. Grid 256. ----------------
__global__ void __launch_bounds__(128) rowsum_kernel(float* __restrict__ out_w)
{
    const int tid  = threadIdx.x;
    const int lane = tid & 31;
    const int row  = blockIdx.x*4 + (tid >> 5);

    const float4* src = (const float4*)(g_E + (size_t)row*NS);
    float4 v[8];
    float s = 0.f;
    #pragma unroll
    for (int i = 0; i < 8; i++) {
        v[i] = src[lane + 32*i];
        s += (v[i].x + v[i].y) + (v[i].z + v[i].w);
    }
    #pragma unroll
    for (int o = 16; o > 0; o >>= 1) s += __shfl_xor_sync(0xffffffffu, s, o);
    const float inv = 1.0f / s;
    if (lane == 0) g_inv[row] = inv;

    float4* dst = (float4*)(out_w + (size_t)row*NS);
    #pragma unroll
    for (int i = 0; i < 8; i++) {
        v[i].x *= inv; v[i].y *= inv; v[i].z *= inv; v[i].w *= inv;
        dst[lane + 32*i] = v[i];
    }
}

// ---------------- Kernel 4: pgemm — R13 proven, per-half. Grid 256. ----------------
__global__ void __launch_bounds__(256) pgemm_kernel(const float* __restrict__ kv, int bsel)
{
    extern __shared__ float ps[];
    float* kvs = ps;                    // 2 * 32*128
    float* Es  = ps + 2*SK2*128;        // 2 * 32*64

    const int tid = threadIdx.x;
    const int bid = blockIdx.x;         // 256 = 8 qtl * 2 hh * 16 sc
    const int sc  = bid & 15;
    const int hh  = (bid >> 4) & 1;
    const int qtl = bid >> 5;           // 0..7
    const int qt  = bsel*8 + qtl;
    const int row0 = qt * 64;
    const int b   = bsel;
    const int qcol = qtl * 64;
    const int s0  = sc * 64;

    const float* kvg = kv   + ((size_t)b*NS + s0)*KVH + hh*128;
    const float* Eg  = g_ET + ((size_t)b*NS + s0)*NQ + qcol;

    const int tx = tid & 31;
    const int ty = tid >> 5;

    #define ISSUE2(c, buf) { \
        _Pragma("unroll") for (int j = 0; j < 4; j++) { \
            int i = tid + 256*j; int s = i >> 5, h4 = i & 31; \
            cp16(kvs + (buf)*SK2*128 + s*128 + h4*4, \
                 kvg + (size_t)((c)*SK2 + s)*KVH + h4*4); } \
        _Pragma("unroll") for (int j = 0; j < 2; j++) { \
            int i = tid + 256*j; int s = i >> 4, q4 = i & 15; \
            cp16(Es + (buf)*SK2*64 + s*64 + q4*4, \
                 Eg + (size_t)((c)*SK2 + s)*NQ + q4*4); } \
        cp_commit(); }

    ISSUE2(0, 0);
    ISSUE2(1, 1);

    float2 acc[8][2];
    #pragma unroll
    for (int i = 0; i < 8; i++) { acc[i][0] = make_float2(0.f,0.f); acc[i][1] = make_float2(0.f,0.f); }

    #pragma unroll
    for (int c = 0; c < 2; c++) {
        if (c == 0) cp_wait1(); else cp_wait0();
        __syncthreads();
        const float* kvb = kvs + c*SK2*128;
        const float* Eb  = Es  + c*SK2*64;
        #pragma unroll 8
        for (int k = 0; k < SK2; k++) {
            float4 k4 = ((const float4*)(kvb + k*128))[tx];
            float4 e0 = ((const float4*)(Eb  + k*64))[ty*2];
            float4 e1 = ((const float4*)(Eb  + k*64))[ty*2 + 1];
            float2 kp0 = make_float2(k4.x, k4.y);
            float2 kp1 = make_float2(k4.z, k4.w);
            float ev[8] = { e0.x, e0.y, e0.z, e0.w, e1.x, e1.y, e1.z, e1.w };
            #pragma unroll
            for (int qi = 0; qi < 8; qi++) {
                float2 eb = make_float2(ev[qi], ev[qi]);
                acc[qi][0] = ffma2(kp0, eb, acc[qi][0]);
                acc[qi][1] = ffma2(kp1, eb, acc[qi][1]);
            }
        }
        __syncthreads();
    }

    float* pb = g_part + ((size_t)sc*(NB*NQ) + row0 + ty*8)*KVH + hh*128 + tx*4;
    #pragma unroll
    for (int qi = 0; qi < 8; qi++)
        *(float4*)(pb + (size_t)qi*KVH) =
            make_float4(acc[qi][0].x, acc[qi][0].y, acc[qi][1].x, acc[qi][1].y);
    #undef ISSUE2
}

// ---------------- Kernel 5: combine 16 partials + normalize (L2-resident) ----------------
__global__ void __launch_bounds__(256) combine_kernel(float* __restrict__ out_o)
{
    const int idx = blockIdx.x*256 + threadIdx.x;
    const int row = idx >> 6;
    const float inv = g_inv[row];
    float4 s = make_float4(0.f,0.f,0.f,0.f);
    #pragma unroll
    for (int c = 0; c < NSC; c++) {
        float4 p = ((const float4*)g_part)[(size_t)c*(NB*NQ*KVH/4) + idx];
        s.x += p.x; s.y += p.y; s.z += p.z; s.w += p.w;
    }
    s.x *= inv; s.y *= inv; s.z *= inv; s.w *= inv;
    ((float4*)out_o)[idx] = s;
}

extern "C" void kernel_launch(void* const* d_in, const int* in_sizes, int n_in,
                              void* d_out, int out_size)
{
    const float* kv  = (const float*)d_in[0];
    const float* qy  = (const float*)d_in[1];
    const float* Wkv = (const float*)d_in[2];
    const float* bkv = (const float*)d_in[3];
    const float* Wq  = (const float*)d_in[4];
    const float* bq  = (const float*)d_in[5];
    const float* wv  = (const float*)d_in[6];
    const float* bv  = (const float*)d_in[7];

    float* out_o = (float*)d_out;
    float* out_w = out_o + NB*NQ*KVH;

    const int pg_smem = (2*SK2*128 + 2*SK2*64) * 4;   // 48KB

    static cudaStream_t s1 = nullptr;
    static cudaEvent_t evA = nullptr, evB = nullptr, evS0 = nullptr, evS1 = nullptr, evG = nullptr;
    if (!s1) {
        cudaStreamCreateWithFlags(&s1, cudaStreamNonBlocking);
        cudaEventCreateWithFlags(&evA,  cudaEventDisableTiming);
        cudaEventCreateWithFlags(&evB,  cudaEventDisableTiming);
        cudaEventCreateWithFlags(&evS0, cudaEventDisableTiming);
        cudaEventCreateWithFlags(&evS1, cudaEventDisableTiming);
        cudaEventCreateWithFlags(&evG,  cudaEventDisableTiming);
        cudaFuncSetAttribute(pgemm_kernel, cudaFuncAttributeMaxDynamicSharedMemorySize, pg_smem);
    }

    // stage 0: proj half-0 on s0 (kv rowblk 0..31, q rowblk 64..79)
    proj_kernel<<<192, 256>>>(kv, qy, Wkv, Wq, 0, 64);
    cudaEventRecord(evA, 0);

    // proj half-1 on s1 (kv rowblk 32..63, q rowblk 80..95), overlaps score_b0
    cudaStreamWaitEvent(s1, evA, 0);
    proj_kernel<<<192, 256, 0, s1>>>(kv, qy, Wkv, Wq, 32, 80);
    cudaEventRecord(evB, s1);

    // score half-0 (after proj_b0 by stream order)
    score_kernel<<<1024, 256>>>(wv, bv, bkv, bq, 0);
    cudaEventRecord(evS0, 0);

    // pgemm half-0 on s1 (after proj_b1 by stream order + score_b0), overlaps score_b1
    cudaStreamWaitEvent(s1, evS0, 0);
    pgemm_kernel<<<256, 256, pg_smem, s1>>>(kv, 0);

    // score half-1 (needs proj_b1)
    cudaStreamWaitEvent((cudaStream_t)0, evB, 0);
    score_kernel<<<1024, 256>>>(wv, bv, bkv, bq, 1);
    cudaEventRecord(evS1, 0);

    // pgemm half-1 on s1, overlaps rowsum
    cudaStreamWaitEvent(s1, evS1, 0);
    pgemm_kernel<<<256, 256, pg_smem, s1>>>(kv, 1);
    cudaEventRecord(evG, s1);

    // rowsum (both halves) on s0, concurrent with pgemm_b1
    rowsum_kernel<<<256, 128>>>(out_w);

    // join: combine needs all partials + g_inv
    cudaStreamWaitEvent((cudaStream_t)0, evG, 0);
    combine_kernel<<<256, 256>>>(out_o);
}